// round 6
// baseline (speedup 1.0000x reference)
#include <cuda_runtime.h>
#include <math.h>
#include <stdint.h>

// Fixed problem shapes
#define EE 400000
#define NN 50000
#define RR 6
#define HH 128
#define DD 256

// Rounded weights: w_up [128,256] then Ws [3][256,256]
__device__ float g_wr[(size_t)HH * DD + 3 * (size_t)DD * DD];

// SMEM layout (floats):
//   tbuf: 128 rows x TSTR(260)  = 33280 floats (133120 B)  [h / t resident]
//   wbuf0: 32 x WSTR(264)       =  8448 floats (33792 B)
//   wbuf1: 32 x WSTR(264)       =  8448 floats (33792 B)
#define TSTR 260
#define WSTR 264
#define WBUF_FL 8448
#define WOFF_FL 33280
#define SMEM_BYTES 200704

// ------------------------------------------------------------------
__device__ __forceinline__ float tf32r(float f) {
    uint32_t u;
    asm("cvt.rna.tf32.f32 %0, %1;" : "=r"(u) : "f"(f));
    return __uint_as_float(u);
}
__device__ __forceinline__ uint32_t smem_u32(const void* p) {
    uint32_t a;
    asm("{ .reg .u64 t; cvta.to.shared.u64 t, %1; cvt.u32.u64 %0, t; }"
        : "=r"(a) : "l"(p));
    return a;
}
__device__ __forceinline__ void mma_tf32(float* c, const uint32_t* a,
                                         const uint32_t* b) {
    asm volatile(
        "mma.sync.aligned.m16n8k8.row.col.f32.tf32.tf32.f32 "
        "{%0,%1,%2,%3}, {%4,%5,%6,%7}, {%8,%9}, {%0,%1,%2,%3};"
        : "+f"(c[0]), "+f"(c[1]), "+f"(c[2]), "+f"(c[3])
        : "r"(a[0]), "r"(a[1]), "r"(a[2]), "r"(a[3]), "r"(b[0]), "r"(b[1]));
}
__device__ __forceinline__ float silu(float v) {
    return __fdividef(v, 1.f + __expf(-v));
}
#define CP16(dst, src) \
    asm volatile("cp.async.cg.shared.global [%0], [%1], 16;" :: "r"(dst), "l"(src))
#define CPCOMMIT() asm volatile("cp.async.commit_group;" ::: "memory")
#define CPWAIT(n)  asm volatile("cp.async.wait_group %0;" :: "n"(n) : "memory")

// ------------------------------------------------------------------
__global__ void zero_kernel(float4* p, int n4) {
    int i = blockIdx.x * blockDim.x + threadIdx.x;
    if (i < n4) p[i] = make_float4(0.f, 0.f, 0.f, 0.f);
}

__global__ void round_weights(const float* __restrict__ wup,
                              const float* __restrict__ Ws,
                              float* __restrict__ dst) {
    int i = blockIdx.x * blockDim.x + threadIdx.x;
    const int n1 = HH * DD;
    const int tot = n1 + 3 * DD * DD;
    if (i < n1) dst[i] = tf32r(wup[i]);
    else if (i < tot) dst[i] = tf32r(Ws[i - n1]);
}

// ------------------------------------------------------------------
// weight chunk loader: 32 rows x 256 cols of W (row-major [K,256]) -> wbuf
__device__ __forceinline__ void load_wchunk(uint32_t wb, const float* W, int k0) {
    const int tid = threadIdx.x;
#pragma unroll
    for (int it = 0; it < 4; it++) {
        int q = tid + it * 512;
        int row = q >> 6, c4 = (q & 63) << 2;
        uint32_t dst = wb + (uint32_t)(row * WSTR + c4) * 4;
        const float* src = W + (size_t)(k0 + row) * DD + c4;
        CP16(dst, src);
    }
}

// One layer: acc = tbuf[:,0:K] @ Wchunks ; epilogue into tbuf or out1.
// Assumes chunk0 of W already issued+committed (in wbuf0).
template<int NCH, bool ACT, bool LAST>
__device__ __forceinline__ void run_layer(
    float* sm, uint32_t sb, const float* W, const float* nextW,
    const float* __restrict__ bias, const float* __restrict__ wout,
    float* __restrict__ out1, size_t e0)
{
    const int tid  = threadIdx.x;
    const int warp = tid >> 5, lane = tid & 31;
    const int g = lane >> 2, t = lane & 3;
    const int wm = warp & 1, wn = warp >> 1;          // wn 0..7
    const uint32_t* tb = reinterpret_cast<const uint32_t*>(sm);

    float acc[4][4][4];
#pragma unroll
    for (int i = 0; i < 4; i++)
#pragma unroll
        for (int j = 0; j < 4; j++)
#pragma unroll
            for (int q = 0; q < 4; q++) acc[i][j][q] = 0.f;

#pragma unroll 1
    for (int c = 0; c < NCH; c++) {
        if (c + 1 < NCH) {
            load_wchunk(sb + (uint32_t)(WOFF_FL + ((c + 1) & 1) * WBUF_FL) * 4,
                        W, (c + 1) * 32);
            CPCOMMIT();
            CPWAIT(1);
        } else {
            CPWAIT(0);
        }
        __syncthreads();
        const uint32_t* wb = reinterpret_cast<const uint32_t*>(
            sm + WOFF_FL + (c & 1) * WBUF_FL);
        const int kbase = c * 32;
#pragma unroll
        for (int ks = 0; ks < 4; ks++) {
            const int k = ks * 8;
            uint32_t af[4][4], bf[4][2];
#pragma unroll
            for (int mf = 0; mf < 4; mf++) {
                int r0 = wm * 64 + mf * 16 + g;
                const uint32_t* a0 = tb + r0 * TSTR + kbase + k + t;
                af[mf][0] = a0[0];
                af[mf][1] = a0[8 * TSTR];
                af[mf][2] = a0[4];
                af[mf][3] = a0[8 * TSTR + 4];
            }
#pragma unroll
            for (int nf = 0; nf < 4; nf++) {
                int c0 = wn * 32 + nf * 8 + g;
                bf[nf][0] = wb[(k + t) * WSTR + c0];
                bf[nf][1] = wb[(k + 4 + t) * WSTR + c0];
            }
#pragma unroll
            for (int mf = 0; mf < 4; mf++)
#pragma unroll
                for (int nf = 0; nf < 4; nf++)
                    mma_tf32(acc[mf][nf], af[mf], bf[nf]);
        }
        __syncthreads();
    }

    // prefetch next layer's chunk0 into wbuf0 (free after trailing sync)
    if (nextW) {
        load_wchunk(sb + (uint32_t)WOFF_FL * 4, nextW, 0);
        CPCOMMIT();
    }

    // ---------------- epilogue ----------------
    if (!LAST) {
#pragma unroll
        for (int mf = 0; mf < 4; mf++) {
#pragma unroll
            for (int nf = 0; nf < 4; nf++) {
                int r0 = wm * 64 + mf * 16 + g;
                int cc = wn * 32 + nf * 8 + 2 * t;
                float v0 = acc[mf][nf][0], v1 = acc[mf][nf][1];
                float v2 = acc[mf][nf][2], v3 = acc[mf][nf][3];
                if (ACT) {
                    float b0 = __ldg(bias + cc), b1 = __ldg(bias + cc + 1);
                    v0 = silu(v0 + b0); v1 = silu(v1 + b1);
                    v2 = silu(v2 + b0); v3 = silu(v3 + b1);
                }
                float2 o0 = make_float2(tf32r(v0), tf32r(v1));
                float2 o1 = make_float2(tf32r(v2), tf32r(v3));
                *reinterpret_cast<float2*>(sm + r0 * TSTR + cc) = o0;
                *reinterpret_cast<float2*>(sm + (r0 + 8) * TSTR + cc) = o1;
            }
        }
        __syncthreads();   // t ready for next layer's A reads
    } else {
        float s0[4], s1[4];
#pragma unroll
        for (int mf = 0; mf < 4; mf++) { s0[mf] = 0.f; s1[mf] = 0.f; }
#pragma unroll
        for (int mf = 0; mf < 4; mf++) {
#pragma unroll
            for (int nf = 0; nf < 4; nf++) {
                int cc = wn * 32 + nf * 8 + 2 * t;
                float b0 = __ldg(bias + cc), b1 = __ldg(bias + cc + 1);
                float w0 = __ldg(wout + cc), w1 = __ldg(wout + cc + 1);
                float v0 = silu(acc[mf][nf][0] + b0);
                float v1 = silu(acc[mf][nf][1] + b1);
                float v2 = silu(acc[mf][nf][2] + b0);
                float v3 = silu(acc[mf][nf][3] + b1);
                s0[mf] += v0 * w0 + v1 * w1;
                s1[mf] += v2 * w0 + v3 * w1;
            }
        }
#pragma unroll
        for (int mf = 0; mf < 4; mf++) {
            s0[mf] += __shfl_xor_sync(0xffffffffu, s0[mf], 1);
            s0[mf] += __shfl_xor_sync(0xffffffffu, s0[mf], 2);
            s1[mf] += __shfl_xor_sync(0xffffffffu, s1[mf], 1);
            s1[mf] += __shfl_xor_sync(0xffffffffu, s1[mf], 2);
        }
        float* red = sm + WOFF_FL;     // reuse wbuf0 region: red[row*8 + wn]
        if (t == 0) {
#pragma unroll
            for (int mf = 0; mf < 4; mf++) {
                int rl = wm * 64 + mf * 16 + g;
                red[rl * 8 + wn] = s0[mf];
                red[(rl + 8) * 8 + wn] = s1[mf];
            }
        }
        __syncthreads();
        if (tid < 128) {
            float s = 0.f;
#pragma unroll
            for (int j = 0; j < 8; j++) s += red[tid * 8 + j];
            out1[e0 + tid] = s;
        }
    }
}

// ------------------------------------------------------------------
// Fused: h = (rbf@w_rbf)*x (+ scatter into x_spe), then 4-layer MLP tower
// with t resident in SMEM, final layer fused with @w_out.
__global__ __launch_bounds__(512, 1)
void fused_tower(const float* __restrict__ x,  const float* __restrict__ rbf,
                 const int*   __restrict__ idx, const float* __restrict__ w_rbf,
                 const float* __restrict__ wr,  const float* __restrict__ bs,
                 const float* __restrict__ wout,
                 float* __restrict__ xspe, float* __restrict__ out1)
{
    extern __shared__ float sm[];
    const uint32_t sb = smem_u32(sm);
    const int tid = threadIdx.x;
    const size_t e0 = (size_t)blockIdx.x * 128;

    const float* W0 = wr;                       // [128,256]
    const float* W1 = wr + HH * DD;             // 3 x [256,256]

    // ---- issue x-strip load (128x128) into tbuf ----
    const float* xb = x + e0 * HH;
#pragma unroll
    for (int it = 0; it < 8; it++) {
        int q = tid + it * 512;
        int row = q >> 5, c4 = (q & 31) << 2;
        uint32_t dst = sb + (uint32_t)(row * TSTR + c4) * 4;
        CP16(dst, xb + (size_t)row * HH + c4);
    }
    CPCOMMIT();
    // ---- issue W_up chunk0 (overlaps h compute) ----
    load_wchunk(sb + (uint32_t)WOFF_FL * 4, W0, 0);
    CPCOMMIT();
    CPWAIT(1);                                  // x landed
    __syncthreads();

    // ---- h = (rbf@w_rbf)*x in-place; fp32 scatter-add; store tf32(h) ----
    {
        const int r = tid >> 2;
        const int cg = (tid & 3) << 5;
        const float* rb = rbf + (e0 + r) * RR;
        float r0 = __ldg(rb + 0), r1 = __ldg(rb + 1), r2 = __ldg(rb + 2);
        float r3 = __ldg(rb + 3), r4 = __ldg(rb + 4), r5 = __ldg(rb + 5);
        const int node = __ldg(idx + e0 + r);
        float* trow = sm + r * TSTR;
        float* xd = xspe + (size_t)node * HH;
#pragma unroll
        for (int cc = 0; cc < 32; cc += 4) {
            int c = cg + cc;
            float4 xv = *reinterpret_cast<float4*>(trow + c);
            float4 w0 = __ldg((const float4*)(w_rbf + 0 * HH + c));
            float4 w1 = __ldg((const float4*)(w_rbf + 1 * HH + c));
            float4 w2 = __ldg((const float4*)(w_rbf + 2 * HH + c));
            float4 w3 = __ldg((const float4*)(w_rbf + 3 * HH + c));
            float4 w4 = __ldg((const float4*)(w_rbf + 4 * HH + c));
            float4 w5 = __ldg((const float4*)(w_rbf + 5 * HH + c));
            float4 h;
            h.x = (r0*w0.x + r1*w1.x + r2*w2.x + r3*w3.x + r4*w4.x + r5*w5.x) * xv.x;
            h.y = (r0*w0.y + r1*w1.y + r2*w2.y + r3*w3.y + r4*w4.y + r5*w5.y) * xv.y;
            h.z = (r0*w0.z + r1*w1.z + r2*w2.z + r3*w3.z + r4*w4.z + r5*w5.z) * xv.z;
            h.w = (r0*w0.w + r1*w1.w + r2*w2.w + r3*w3.w + r4*w4.w + r5*w5.w) * xv.w;
            float4 hr;
            hr.x = tf32r(h.x); hr.y = tf32r(h.y);
            hr.z = tf32r(h.z); hr.w = tf32r(h.w);
            *reinterpret_cast<float4*>(trow + c) = hr;
            atomicAdd(xd + c + 0, h.x);
            atomicAdd(xd + c + 1, h.y);
            atomicAdd(xd + c + 2, h.z);
            atomicAdd(xd + c + 3, h.w);
        }
    }
    __syncthreads();

    // ---- 4-layer tower, t resident in SMEM ----
    run_layer<4, false, false>(sm, sb, W0, W1 + 0 * DD * DD,
                               nullptr, nullptr, nullptr, e0);
    run_layer<8, true, false>(sm, sb, W1 + 0 * DD * DD, W1 + 1 * DD * DD,
                              bs + 0 * DD, nullptr, nullptr, e0);
    run_layer<8, true, false>(sm, sb, W1 + 1 * DD * DD, W1 + 2 * DD * DD,
                              bs + 1 * DD, nullptr, nullptr, e0);
    run_layer<8, true, true>(sm, sb, W1 + 2 * DD * DD, nullptr,
                             bs + 2 * DD, wout, out1, e0);
}

// ------------------------------------------------------------------
extern "C" void kernel_launch(void* const* d_in, const int* in_sizes, int n_in,
                              void* d_out, int out_size) {
    const float* x     = (const float*)d_in[0];   // [E,128]
    const float* rbf   = (const float*)d_in[1];   // [E,6]
    const int*   idx   = (const int*)  d_in[2];   // [E]
    const float* w_rbf = (const float*)d_in[3];   // [6,128]
    const float* w_up  = (const float*)d_in[4];   // [128,256]
    const float* Ws    = (const float*)d_in[5];   // [3,256,256]
    const float* bs    = (const float*)d_in[6];   // [3,256]
    const float* w_out = (const float*)d_in[7];   // [256,1]

    const int E = in_sizes[2];                    // 400000

    float* out_f = (float*)d_out;
    float* xspe  = out_f;                         // [N,128]
    float* out1  = out_f + (size_t)NN * HH;       // [E]

    float* pwr;
    cudaGetSymbolAddress((void**)&pwr, g_wr);

    cudaFuncSetAttribute(fused_tower,
                         cudaFuncAttributeMaxDynamicSharedMemorySize, SMEM_BYTES);

    // 0) round weights to tf32 (RNA)
    {
        int tot = HH * DD + 3 * DD * DD;
        round_weights<<<(tot + 255) / 256, 256>>>(w_up, Ws, pwr);
    }
    // 1) zero x_spe (out1 is fully written by fused kernel)
    {
        int n4 = (NN * HH) / 4;
        zero_kernel<<<(n4 + 255) / 256, 256>>>((float4*)xspe, n4);
    }
    // 2) fused h + scatter + 4-layer tower + out projection
    {
        fused_tower<<<E / 128, 512, SMEM_BYTES>>>(
            x, rbf, idx, w_rbf, pwr, bs, w_out, xspe, out1);
    }
}